// round 4
// baseline (speedup 1.0000x reference)
#include <cuda_runtime.h>
#include <cuda_fp16.h>

#define B_  4
#define Q_  512
#define KK_ 1024
#define D_  512
#define H_  128
#define DV_ 512

// Scratch (device globals; no allocation allowed in kernel_launch)
__device__ __half g_qph[B_ * Q_ * H_];    // 512 KB
__device__ __half g_kph[B_ * KK_ * H_];   // 1 MB
__device__ float  g_attn[B_ * Q_ * KK_];  // 8 MB

__device__ __forceinline__ __half2 tanh_h2(__half2 x) {
    unsigned xi = *(unsigned*)&x, yi;
    asm("tanh.approx.f16x2 %0, %1;" : "=r"(yi) : "r"(xi));
    return *(__half2*)&yi;
}
__device__ __forceinline__ __half2 as_h2(unsigned u) { return *(__half2*)&u; }

// ---- packed f32x2 helpers (sm_103a: FFMA2 reachable only via PTX) ----
__device__ __forceinline__ unsigned long long bcast2(float a) {
    unsigned long long r;
    asm("mov.b64 %0, {%1, %1};" : "=l"(r) : "f"(a));
    return r;
}
__device__ __forceinline__ void fma2(unsigned long long& d,
                                     unsigned long long a, unsigned long long b) {
    asm("fma.rn.f32x2 %0, %1, %2, %3;" : "=l"(d) : "l"(a), "l"(b), "l"(d));
}
__device__ __forceinline__ float2 unpack2(unsigned long long v) {
    float2 f;
    asm("mov.b64 {%0, %1}, %2;" : "=f"(f.x), "=f"(f.y) : "l"(v));
    return f;
}

// ---- cp.async helpers ----
__device__ __forceinline__ void cp_async16(void* smem, const void* gmem) {
    unsigned saddr = (unsigned)__cvta_generic_to_shared(smem);
    asm volatile("cp.async.cg.shared.global [%0], [%1], 16;\n" :: "r"(saddr), "l"(gmem));
}
__device__ __forceinline__ void cp_commit() {
    asm volatile("cp.async.commit_group;\n");
}
template<int N> __device__ __forceinline__ void cp_wait() {
    asm volatile("cp.async.wait_group %0;\n" :: "n"(N));
}

// ============================================================================
// Kernel 1: projections -> HALF outputs. C[row,h] = sum_d A[row,d]*W[d,h]
// BM=64, BN=64, BK=32, 128 threads, micro 4x8. A staged transposed (ldg+sts).
// Grid 192: blk<64 -> qp (32 row-tiles x 2 col-halves), else kp (64 x 2).
// ============================================================================
__global__ __launch_bounds__(128) void proj_kernel(
    const float* __restrict__ Aq, const float* __restrict__ Ak,
    const float* __restrict__ Wq, const float* __restrict__ Wk)
{
    __shared__ float At[2][32 * 68];   // [k][row], stride 68 (16B-aligned, low-conflict)
    __shared__ float Ws[2][32 * 68];   // [k][col], stride 68

    int blk = blockIdx.x;
    const float* A; const float* W; __half* C; int rowbase, nb;
    if (blk < 64) { A = Aq; W = Wq; C = g_qph; rowbase = (blk >> 1) * 64; nb = (blk & 1) * 64; }
    else { int t = blk - 64; A = Ak; W = Wk; C = g_kph; rowbase = (t >> 1) * 64; nb = (t & 1) * 64; }

    int tid = threadIdx.x;
    int tx = tid & 7;          // col group: nb + tx*8 .. +7
    int ty = tid >> 3;         // row group: ty*4 .. +3

    unsigned long long acc[4][4];
#pragma unroll
    for (int i = 0; i < 4; i++)
#pragma unroll
        for (int j = 0; j < 4; j++) acc[i][j] = 0ull;

    int ar0 = tid >> 3;            // A load: base row (+16 per i)
    int akc = (tid & 7) << 2;      // A load: k-col
    int wr0 = tid >> 4;            // W load: base k-row (+8 per i)
    int wc  = (tid & 15) << 2;     // W load: col

    float4 av[4];

#define LDG_A(kk) { _Pragma("unroll") for (int i_ = 0; i_ < 4; i_++)            \
        av[i_] = *(const float4*)(A + (size_t)(rowbase + ar0 + i_ * 16) * D_ + (kk) + akc); }
#define STS_A(buf) { _Pragma("unroll") for (int i_ = 0; i_ < 4; i_++) {         \
        At[buf][(akc + 0) * 68 + ar0 + i_ * 16] = av[i_].x;                     \
        At[buf][(akc + 1) * 68 + ar0 + i_ * 16] = av[i_].y;                     \
        At[buf][(akc + 2) * 68 + ar0 + i_ * 16] = av[i_].z;                     \
        At[buf][(akc + 3) * 68 + ar0 + i_ * 16] = av[i_].w; } }
#define CPA_W(kk, buf) { _Pragma("unroll") for (int i_ = 0; i_ < 4; i_++) {     \
        int r_ = wr0 + i_ * 8;                                                  \
        cp_async16(&Ws[buf][r_ * 68 + wc], W + (size_t)((kk) + r_) * H_ + nb + wc); } \
        cp_commit(); }

    LDG_A(0); CPA_W(0, 0); STS_A(0);

    for (int s = 0; s < 16; s++) {
        int buf = s & 1;
        cp_wait<0>();
        __syncthreads();
        bool nxt = (s + 1 < 16);
        if (nxt) { LDG_A((s + 1) * 32); CPA_W((s + 1) * 32, buf ^ 1); }
#pragma unroll
        for (int k = 0; k < 32; k++) {
            float4 af = *(const float4*)&At[buf][k * 68 + ty * 4];
            ulonglong2 b0 = *(const ulonglong2*)&Ws[buf][k * 68 + tx * 8];
            ulonglong2 b1 = *(const ulonglong2*)&Ws[buf][k * 68 + tx * 8 + 4];
            unsigned long long pa;
            pa = bcast2(af.x);
            fma2(acc[0][0], pa, b0.x); fma2(acc[0][1], pa, b0.y);
            fma2(acc[0][2], pa, b1.x); fma2(acc[0][3], pa, b1.y);
            pa = bcast2(af.y);
            fma2(acc[1][0], pa, b0.x); fma2(acc[1][1], pa, b0.y);
            fma2(acc[1][2], pa, b1.x); fma2(acc[1][3], pa, b1.y);
            pa = bcast2(af.z);
            fma2(acc[2][0], pa, b0.x); fma2(acc[2][1], pa, b0.y);
            fma2(acc[2][2], pa, b1.x); fma2(acc[2][3], pa, b1.y);
            pa = bcast2(af.w);
            fma2(acc[3][0], pa, b0.x); fma2(acc[3][1], pa, b0.y);
            fma2(acc[3][2], pa, b1.x); fma2(acc[3][3], pa, b1.y);
        }
        if (nxt) STS_A(buf ^ 1);
    }
#undef LDG_A
#undef STS_A
#undef CPA_W

#pragma unroll
    for (int i = 0; i < 4; i++) {
        float2 p0 = unpack2(acc[i][0]);
        float2 p1 = unpack2(acc[i][1]);
        float2 p2 = unpack2(acc[i][2]);
        float2 p3 = unpack2(acc[i][3]);
        __half2 h0 = __floats2half2_rn(p0.x, p0.y);
        __half2 h1 = __floats2half2_rn(p1.x, p1.y);
        __half2 h2 = __floats2half2_rn(p2.x, p2.y);
        __half2 h3 = __floats2half2_rn(p3.x, p3.y);
        uint4 u = make_uint4(*(unsigned*)&h0, *(unsigned*)&h1,
                             *(unsigned*)&h2, *(unsigned*)&h3);
        *(uint4*)(C + (size_t)(rowbase + ty * 4 + i) * H_ + nb + tx * 8) = u;
    }
}

// ============================================================================
// Kernel 2: scores + softmax. 128 threads = 4 warps, warp w owns q-row.
// Grid = B*Q/4 = 512. q/k in fp16: HADD2 + tanh.f16x2, fp32 accumulate.
// kp chunks (32 rows x 128 halves) double-buffered via cp.async.
// ============================================================================
__global__ __launch_bounds__(128) void score_softmax_kernel(const float* __restrict__ wv_g)
{
    __shared__ __half kp_sm[2][32 * 128];
    __shared__ __half q_sm[4 * 128];
    __shared__ float  w_sm[128];

    int tid = threadIdx.x;
    int w = tid >> 5;
    int l = tid & 31;

    int qb = blockIdx.x * 4;
    int b  = qb >> 9;
    int q0 = qb & 511;

    // stage 4 q-rows (half) + w_v (f32); first __syncthreads covers these
    if (tid < 64) {
        int r = tid >> 4, c = (tid & 15) << 3;
        *(uint4*)&q_sm[r * 128 + c] =
            *(const uint4*)&g_qph[(size_t)(b * Q_ + q0 + r) * H_ + c];
    }
    if (tid >= 96) {
        int t = tid - 96;
        *(float4*)&w_sm[t * 4] = *(const float4*)&wv_g[t * 4];
    }

    const __half* kp_base = g_kph + (size_t)b * KK_ * H_;

#define KP_STAGE(ch, buf) { _Pragma("unroll") for (int i_ = 0; i_ < 4; i_++) {  \
        int idx_ = tid + i_ * 128;                                              \
        int r_ = idx_ >> 4, c_ = (idx_ & 15) << 3;                              \
        cp_async16(&kp_sm[buf][r_ * 128 + c_],                                  \
                   kp_base + (size_t)((ch) * 32 + r_) * H_ + c_); }             \
        cp_commit(); }

    float s[32];

    KP_STAGE(0, 0);
    for (int ch = 0; ch < 32; ch++) {
        int buf = ch & 1;
        cp_wait<0>();
        __syncthreads();
        if (ch + 1 < 32) KP_STAGE(ch + 1, buf ^ 1);

        const uint4* kr = (const uint4*)&kp_sm[buf][l * 128];
        const uint4* qr = (const uint4*)&q_sm[w * 128];
        float s0 = 0.f, s1 = 0.f, s2 = 0.f, s3 = 0.f;
        float s4 = 0.f, s5 = 0.f, s6 = 0.f, s7 = 0.f;
#pragma unroll
        for (int h8 = 0; h8 < 16; h8++) {
            uint4 kv = kr[h8];
            uint4 qv = qr[h8];
            float2 f0 = __half22float2(tanh_h2(__hadd2(as_h2(qv.x), as_h2(kv.x))));
            float2 f1 = __half22float2(tanh_h2(__hadd2(as_h2(qv.y), as_h2(kv.y))));
            float2 f2 = __half22float2(tanh_h2(__hadd2(as_h2(qv.z), as_h2(kv.z))));
            float2 f3 = __half22float2(tanh_h2(__hadd2(as_h2(qv.w), as_h2(kv.w))));
            float4 w0 = *(const float4*)&w_sm[h8 * 8];
            float4 w1 = *(const float4*)&w_sm[h8 * 8 + 4];
            s0 += w0.x * f0.x; s1 += w0.y * f0.y;
            s2 += w0.z * f1.x; s3 += w0.w * f1.y;
            s4 += w1.x * f2.x; s5 += w1.y * f2.y;
            s6 += w1.z * f3.x; s7 += w1.w * f3.y;
        }
        s[ch] = ((s0 + s1) + (s2 + s3)) + ((s4 + s5) + (s6 + s7));
    }
#undef KP_STAGE

    // softmax: lane l holds scores for k = ch*32 + l
    float m = -1e30f;
#pragma unroll
    for (int j = 0; j < 32; j++) m = fmaxf(m, s[j]);
#pragma unroll
    for (int o = 16; o; o >>= 1) m = fmaxf(m, __shfl_xor_sync(0xffffffffu, m, o));
    float sum = 0.f;
#pragma unroll
    for (int j = 0; j < 32; j++) { s[j] = __expf(s[j] - m); sum += s[j]; }
#pragma unroll
    for (int o = 16; o; o >>= 1) sum += __shfl_xor_sync(0xffffffffu, sum, o);
    float inv = 1.0f / sum;

    float* arow = g_attn + (size_t)(b * Q_ + q0 + w) * KK_;
#pragma unroll
    for (int j = 0; j < 32; j++) arow[j * 32 + l] = s[j] * inv;
}

// ============================================================================
// Kernel 3: out[b] = attn[b] @ values[b]. M=512, N=512, Kd=1024 per batch.
// Same template as proj: BM=64, BN=64, BK=32, 128 threads, micro 4x8,
// A (attn) transposed staging, B (values) via cp.async. Grid (8,8,4)=256.
// ============================================================================
__global__ __launch_bounds__(128) void av_gemm_kernel(
    const float* __restrict__ values, float* __restrict__ out)
{
    __shared__ float At[2][32 * 68];
    __shared__ float Bs[2][32 * 68];

    int b  = blockIdx.z;
    int mb = blockIdx.y * 64;
    int nb = blockIdx.x * 64;

    const float* Ab = g_attn + (size_t)b * Q_ * KK_;     // [512,1024]
    const float* Bb = values + (size_t)b * KK_ * DV_;    // [1024,512]
    float* Ob = out + (size_t)b * Q_ * DV_;

    int tid = threadIdx.x;
    int tx = tid & 7;
    int ty = tid >> 3;

    unsigned long long acc[4][4];
#pragma unroll
    for (int i = 0; i < 4; i++)
#pragma unroll
        for (int j = 0; j < 4; j++) acc[i][j] = 0ull;

    int ar0 = tid >> 3;
    int akc = (tid & 7) << 2;
    int wr0 = tid >> 4;
    int wc  = (tid & 15) << 2;

    float4 av[4];

#define LDG_A(kk) { _Pragma("unroll") for (int i_ = 0; i_ < 4; i_++)            \
        av[i_] = *(const float4*)(Ab + (size_t)(mb + ar0 + i_ * 16) * KK_ + (kk) + akc); }
#define STS_A(buf) { _Pragma("unroll") for (int i_ = 0; i_ < 4; i_++) {         \
        At[buf][(akc + 0) * 68 + ar0 + i_ * 16] = av[i_].x;                     \
        At[buf][(akc + 1) * 68 + ar0 + i_ * 16] = av[i_].y;                     \
        At[buf][(akc + 2) * 68 + ar0 + i_ * 16] = av[i_].z;                     \
        At[buf][(akc + 3) * 68 + ar0 + i_ * 16] = av[i_].w; } }
#define CPA_B(kk, buf) { _Pragma("unroll") for (int i_ = 0; i_ < 4; i_++) {     \
        int r_ = wr0 + i_ * 8;                                                  \
        cp_async16(&Bs[buf][r_ * 68 + wc], Bb + (size_t)((kk) + r_) * DV_ + nb + wc); } \
        cp_commit(); }

    LDG_A(0); CPA_B(0, 0); STS_A(0);

    for (int s = 0; s < 32; s++) {
        int buf = s & 1;
        cp_wait<0>();
        __syncthreads();
        bool nxt = (s + 1 < 32);
        if (nxt) { LDG_A((s + 1) * 32); CPA_B((s + 1) * 32, buf ^ 1); }
#pragma unroll
        for (int k = 0; k < 32; k++) {
            float4 af = *(const float4*)&At[buf][k * 68 + ty * 4];
            ulonglong2 b0 = *(const ulonglong2*)&Bs[buf][k * 68 + tx * 8];
            ulonglong2 b1 = *(const ulonglong2*)&Bs[buf][k * 68 + tx * 8 + 4];
            unsigned long long pa;
            pa = bcast2(af.x);
            fma2(acc[0][0], pa, b0.x); fma2(acc[0][1], pa, b0.y);
            fma2(acc[0][2], pa, b1.x); fma2(acc[0][3], pa, b1.y);
            pa = bcast2(af.y);
            fma2(acc[1][0], pa, b0.x); fma2(acc[1][1], pa, b0.y);
            fma2(acc[1][2], pa, b1.x); fma2(acc[1][3], pa, b1.y);
            pa = bcast2(af.z);
            fma2(acc[2][0], pa, b0.x); fma2(acc[2][1], pa, b0.y);
            fma2(acc[2][2], pa, b1.x); fma2(acc[2][3], pa, b1.y);
            pa = bcast2(af.w);
            fma2(acc[3][0], pa, b0.x); fma2(acc[3][1], pa, b0.y);
            fma2(acc[3][2], pa, b1.x); fma2(acc[3][3], pa, b1.y);
        }
        if (nxt) STS_A(buf ^ 1);
    }
#undef LDG_A
#undef STS_A
#undef CPA_B

#pragma unroll
    for (int i = 0; i < 4; i++) {
        float2 p0 = unpack2(acc[i][0]);
        float2 p1 = unpack2(acc[i][1]);
        float2 p2 = unpack2(acc[i][2]);
        float2 p3 = unpack2(acc[i][3]);
        float* orow = Ob + (size_t)(mb + ty * 4 + i) * DV_ + nb + tx * 8;
        *(float4*)(orow)     = make_float4(p0.x, p0.y, p1.x, p1.y);
        *(float4*)(orow + 4) = make_float4(p2.x, p2.y, p3.x, p3.y);
    }
}

// ----------------------------------------------------------------------------
extern "C" void kernel_launch(void* const* d_in, const int* in_sizes, int n_in,
                              void* d_out, int out_size)
{
    const float* queries = (const float*)d_in[0];  // [4,512,512]
    const float* keys    = (const float*)d_in[1];  // [4,1024,512]
    const float* values  = (const float*)d_in[2];  // [4,1024,512]
    const float* W_q     = (const float*)d_in[3];  // [512,128]
    const float* W_k     = (const float*)d_in[4];  // [512,128]
    const float* w_v     = (const float*)d_in[5];  // [128]
    float* out = (float*)d_out;                    // [4,512,512]

    proj_kernel<<<192, 128>>>(queries, keys, W_q, W_k);
    score_softmax_kernel<<<512, 128>>>(w_v);
    dim3 g3(8, 8, 4);
    av_gemm_kernel<<<g3, 128>>>(values, out);
}

// round 5
// speedup vs baseline: 1.2067x; 1.2067x over previous
#include <cuda_runtime.h>
#include <cuda_fp16.h>

#define B_  4
#define Q_  512
#define KK_ 1024
#define D_  512
#define H_  128
#define DV_ 512

// Scratch (device globals; no allocation allowed in kernel_launch)
__device__ __half g_qph[B_ * Q_ * H_];    // 512 KB
__device__ __half g_kph[B_ * KK_ * H_];   // 1 MB
__device__ float  g_attn[B_ * Q_ * KK_];  // 8 MB

__device__ __forceinline__ __half2 tanh_h2(__half2 x) {
    unsigned xi = *(unsigned*)&x, yi;
    asm("tanh.approx.f16x2 %0, %1;" : "=r"(yi) : "r"(xi));
    return *(__half2*)&yi;
}
__device__ __forceinline__ __half2 as_h2(unsigned u) { return *(__half2*)&u; }

// ---- packed f32x2 helpers (sm_103a: FFMA2 reachable only via PTX) ----
__device__ __forceinline__ unsigned long long bcast2(float a) {
    unsigned long long r;
    asm("mov.b64 %0, {%1, %1};" : "=l"(r) : "f"(a));
    return r;
}
__device__ __forceinline__ void fma2(unsigned long long& d,
                                     unsigned long long a, unsigned long long b) {
    asm("fma.rn.f32x2 %0, %1, %2, %3;" : "=l"(d) : "l"(a), "l"(b), "l"(d));
}
__device__ __forceinline__ float2 unpack2(unsigned long long v) {
    float2 f;
    asm("mov.b64 {%0, %1}, %2;" : "=f"(f.x), "=f"(f.y) : "l"(v));
    return f;
}

// ---- cp.async helpers ----
__device__ __forceinline__ void cp_async16(void* smem, const void* gmem) {
    unsigned saddr = (unsigned)__cvta_generic_to_shared(smem);
    asm volatile("cp.async.cg.shared.global [%0], [%1], 16;\n" :: "r"(saddr), "l"(gmem));
}
__device__ __forceinline__ void cp_commit() {
    asm volatile("cp.async.commit_group;\n");
}
template<int N> __device__ __forceinline__ void cp_wait() {
    asm volatile("cp.async.wait_group %0;\n" :: "n"(N));
}

// ----------------------------------------------------------------------------
// Kernel 1: projections -> HALF out. C[row,h] = sum_d A[row,d]*W[d,h]
// BM=32, BN=64, BK=32, 128 threads, micro 4x4. All staging via cp.async,
// double-buffered with wait<1>. Grid 384 (R3-measured 25.7us).
// ----------------------------------------------------------------------------
__global__ __launch_bounds__(128) void proj_kernel(
    const float* __restrict__ Aq, const float* __restrict__ Ak,
    const float* __restrict__ Wq, const float* __restrict__ Wk)
{
    __shared__ float As[2][32 * 32];
    __shared__ float Ws[2][32 * 64];

    int blk = blockIdx.x;
    const float* A;
    const float* W;
    __half* C;
    int rowbase, nb;
    if (blk < 128) { A = Aq; W = Wq; C = g_qph; rowbase = (blk >> 1) * 32; nb = (blk & 1) * 64; }
    else {
        int t = blk - 128;
        A = Ak; W = Wk; C = g_kph; rowbase = (t >> 1) * 32; nb = (t & 1) * 64;
    }

    int tid = threadIdx.x;
    int tx = tid & 15;            // col group: nb + tx*4
    int ty = tid >> 4;            // row group: ty*4 .. +3

    unsigned long long acc[4][2];
#pragma unroll
    for (int i = 0; i < 4; i++) { acc[i][0] = 0ull; acc[i][1] = 0ull; }

#define PROJ_STAGE(kk, buf)                                                     \
    do {                                                                        \
        _Pragma("unroll")                                                       \
        for (int i_ = 0; i_ < 2; i_++) {                                        \
            int idx_ = tid + i_ * 128;                                          \
            int r_ = idx_ >> 3, c_ = (idx_ & 7) << 2;                           \
            cp_async16(&As[buf][r_ * 32 + c_],                                  \
                       A + (size_t)(rowbase + r_) * D_ + (kk) + c_);            \
        }                                                                       \
        _Pragma("unroll")                                                       \
        for (int i_ = 0; i_ < 4; i_++) {                                        \
            int idx_ = tid + i_ * 128;                                          \
            int r_ = idx_ >> 4, c_ = (idx_ & 15) << 2;                          \
            cp_async16(&Ws[buf][r_ * 64 + c_],                                  \
                       W + (size_t)((kk) + r_) * H_ + nb + c_);                 \
        }                                                                       \
        cp_commit();                                                            \
    } while (0)

    PROJ_STAGE(0, 0);
    for (int s = 0; s < 16; s++) {
        int buf = s & 1;
        if (s + 1 < 16) { PROJ_STAGE((s + 1) * 32, (s + 1) & 1); cp_wait<1>(); }
        else            { cp_wait<0>(); }
        __syncthreads();
#pragma unroll
        for (int k = 0; k < 32; k++) {
            const ulonglong2 bv = *(const ulonglong2*)&Ws[buf][k * 64 + tx * 4];
#pragma unroll
            for (int i = 0; i < 4; i++) {
                unsigned long long pa = bcast2(As[buf][(ty * 4 + i) * 32 + k]);
                fma2(acc[i][0], pa, bv.x);
                fma2(acc[i][1], pa, bv.y);
            }
        }
        __syncthreads();
    }
#undef PROJ_STAGE

#pragma unroll
    for (int i = 0; i < 4; i++) {
        float2 lo = unpack2(acc[i][0]);
        float2 hi = unpack2(acc[i][1]);
        __half2 h0 = __floats2half2_rn(lo.x, lo.y);
        __half2 h1 = __floats2half2_rn(hi.x, hi.y);
        uint2 u = make_uint2(*(unsigned*)&h0, *(unsigned*)&h1);
        *(uint2*)(C + (size_t)(rowbase + ty * 4 + i) * H_ + nb + tx * 4) = u;
    }
}

// ----------------------------------------------------------------------------
// Kernel 2: scores + softmax. 128 threads = 4 warps, warp w owns q-row.
// Grid = B*Q/4 = 512. q/k in fp16: HADD2 + tanh.f16x2 (2 evals per MUFU),
// fp32 accumulate. kp chunks (32 rows x 128 halves = 8KB) double-buffered
// via cp.async with wait<1>.
// ----------------------------------------------------------------------------
__global__ __launch_bounds__(128) void score_softmax_kernel(const float* __restrict__ wv_g)
{
    __shared__ __half kp_sm[2][32 * 128];
    __shared__ __half q_sm[4 * 128];
    __shared__ float  w_sm[128];

    int tid = threadIdx.x;
    int w = tid >> 5;
    int l = tid & 31;

    int qb = blockIdx.x * 4;
    int b  = qb >> 9;
    int q0 = qb & 511;

    // stage 4 q-rows (half) + w_v (f32); first __syncthreads covers these
    if (tid < 64) {
        int r = tid >> 4, c = (tid & 15) << 3;
        *(uint4*)&q_sm[r * 128 + c] =
            *(const uint4*)&g_qph[(size_t)(b * Q_ + q0 + r) * H_ + c];
    }
    if (tid >= 96) {
        int t = tid - 96;
        *(float4*)&w_sm[t * 4] = *(const float4*)&wv_g[t * 4];
    }

    const __half* kp_base = g_kph + (size_t)b * KK_ * H_;

#define KP_STAGE(ch, buf) { _Pragma("unroll") for (int i_ = 0; i_ < 4; i_++) {  \
        int idx_ = tid + i_ * 128;                                              \
        int r_ = idx_ >> 4, c_ = (idx_ & 15) << 3;                              \
        cp_async16(&kp_sm[buf][r_ * 128 + c_],                                  \
                   kp_base + (size_t)((ch) * 32 + r_) * H_ + c_); }             \
        cp_commit(); }

    float s[32];

    KP_STAGE(0, 0);
    for (int ch = 0; ch < 32; ch++) {
        int buf = ch & 1;
        if (ch + 1 < 32) { KP_STAGE(ch + 1, buf ^ 1); cp_wait<1>(); }
        else             { cp_wait<0>(); }
        __syncthreads();

        const uint4* kr = (const uint4*)&kp_sm[buf][l * 128];
        const uint4* qr = (const uint4*)&q_sm[w * 128];
        float s0 = 0.f, s1 = 0.f, s2 = 0.f, s3 = 0.f;
        float s4 = 0.f, s5 = 0.f, s6 = 0.f, s7 = 0.f;
#pragma unroll
        for (int h8 = 0; h8 < 16; h8++) {
            uint4 kv = kr[h8];
            uint4 qv = qr[h8];
            float2 f0 = __half22float2(tanh_h2(__hadd2(as_h2(qv.x), as_h2(kv.x))));
            float2 f1 = __half22float2(tanh_h2(__hadd2(as_h2(qv.y), as_h2(kv.y))));
            float2 f2 = __half22float2(tanh_h2(__hadd2(as_h2(qv.z), as_h2(kv.z))));
            float2 f3 = __half22float2(tanh_h2(__hadd2(as_h2(qv.w), as_h2(kv.w))));
            float4 w0 = *(const float4*)&w_sm[h8 * 8];
            float4 w1 = *(const float4*)&w_sm[h8 * 8 + 4];
            s0 += w0.x * f0.x; s1 += w0.y * f0.y;
            s2 += w0.z * f1.x; s3 += w0.w * f1.y;
            s4 += w1.x * f2.x; s5 += w1.y * f2.y;
            s6 += w1.z * f3.x; s7 += w1.w * f3.y;
        }
        s[ch] = ((s0 + s1) + (s2 + s3)) + ((s4 + s5) + (s6 + s7));
        __syncthreads();
    }
#undef KP_STAGE

    // softmax: lane l holds scores for k = ch*32 + l
    float m = -1e30f;
#pragma unroll
    for (int j = 0; j < 32; j++) m = fmaxf(m, s[j]);
#pragma unroll
    for (int o = 16; o; o >>= 1) m = fmaxf(m, __shfl_xor_sync(0xffffffffu, m, o));
    float sum = 0.f;
#pragma unroll
    for (int j = 0; j < 32; j++) { s[j] = __expf(s[j] - m); sum += s[j]; }
#pragma unroll
    for (int o = 16; o; o >>= 1) sum += __shfl_xor_sync(0xffffffffu, sum, o);
    float inv = 1.0f / sum;

    float* arow = g_attn + (size_t)(b * Q_ + q0 + w) * KK_;
#pragma unroll
    for (int j = 0; j < 32; j++) arow[j * 32 + l] = s[j] * inv;
}

// ----------------------------------------------------------------------------
// Kernel 3: out[b] = attn[b] @ values[b].  M=512, N=512, Kd=1024 per batch.
// R2 version: BM=BN=64, BK=32, 256 threads, micro 4x4 (2 f32x2 pairs),
// all cp.async staging, double-buffered with wait<1>. Grid (8,8,4)=256.
// ----------------------------------------------------------------------------
__global__ __launch_bounds__(256) void av_gemm_kernel(
    const float* __restrict__ values, float* __restrict__ out)
{
    __shared__ float As[2][64 * 32];
    __shared__ float Bs[2][32 * 64];

    int b  = blockIdx.z;
    int mb = blockIdx.y * 64;
    int nb = blockIdx.x * 64;

    const float* Ab = g_attn + (size_t)b * Q_ * KK_;     // [512,1024]
    const float* Bb = values + (size_t)b * KK_ * DV_;    // [1024,512]
    float* Ob = out + (size_t)b * Q_ * DV_;

    int tid = threadIdx.x;
    int tx = tid & 15;     // cols nb + tx*4 .. +3
    int ty = tid >> 4;     // rows mb + ty*4 .. +3

    unsigned long long acc[4][2];
#pragma unroll
    for (int i = 0; i < 4; i++) { acc[i][0] = 0ull; acc[i][1] = 0ull; }

#define AV_STAGE(kk, buf)                                                       \
    do {                                                                        \
        _Pragma("unroll")                                                       \
        for (int i_ = 0; i_ < 2; i_++) {                                        \
            int idx_ = tid + i_ * 256;                                          \
            int r_ = idx_ >> 3, c_ = (idx_ & 7) << 2;                           \
            cp_async16(&As[buf][r_ * 32 + c_],                                  \
                       Ab + (size_t)(mb + r_) * KK_ + (kk) + c_);               \
        }                                                                       \
        _Pragma("unroll")                                                       \
        for (int i_ = 0; i_ < 2; i_++) {                                        \
            int idx_ = tid + i_ * 256;                                          \
            int r_ = idx_ >> 4, c_ = (idx_ & 15) << 2;                          \
            cp_async16(&Bs[buf][r_ * 64 + c_],                                  \
                       Bb + (size_t)((kk) + r_) * DV_ + nb + c_);               \
        }                                                                       \
        cp_commit();                                                            \
    } while (0)

    AV_STAGE(0, 0);
    for (int s = 0; s < 32; s++) {
        int buf = s & 1;
        if (s + 1 < 32) { AV_STAGE((s + 1) * 32, (s + 1) & 1); cp_wait<1>(); }
        else            { cp_wait<0>(); }
        __syncthreads();
#pragma unroll
        for (int k = 0; k < 32; k++) {
            const ulonglong2 bv = *(const ulonglong2*)&Bs[buf][k * 64 + tx * 4];
#pragma unroll
            for (int i = 0; i < 4; i++) {
                unsigned long long pa = bcast2(As[buf][(ty * 4 + i) * 32 + k]);
                fma2(acc[i][0], pa, bv.x);
                fma2(acc[i][1], pa, bv.y);
            }
        }
        __syncthreads();
    }
#undef AV_STAGE

#pragma unroll
    for (int i = 0; i < 4; i++) {
        float2 lo = unpack2(acc[i][0]);
        float2 hi = unpack2(acc[i][1]);
        float4 v = make_float4(lo.x, lo.y, hi.x, hi.y);
        *(float4*)(Ob + (size_t)(mb + ty * 4 + i) * DV_ + nb + tx * 4) = v;
    }
}

// ----------------------------------------------------------------------------
extern "C" void kernel_launch(void* const* d_in, const int* in_sizes, int n_in,
                              void* d_out, int out_size)
{
    const float* queries = (const float*)d_in[0];  // [4,512,512]
    const float* keys    = (const float*)d_in[1];  // [4,1024,512]
    const float* values  = (const float*)d_in[2];  // [4,1024,512]
    const float* W_q     = (const float*)d_in[3];  // [512,128]
    const float* W_k     = (const float*)d_in[4];  // [512,128]
    const float* w_v     = (const float*)d_in[5];  // [128]
    float* out = (float*)d_out;                    // [4,512,512]

    proj_kernel<<<384, 128>>>(queries, keys, W_q, W_k);
    score_softmax_kernel<<<512, 128>>>(w_v);
    dim3 g3(8, 8, 4);
    av_gemm_kernel<<<g3, 256>>>(values, out);
}

// round 10
// speedup vs baseline: 1.8308x; 1.5173x over previous
#include <cuda_runtime.h>
#include <cuda_fp16.h>

#define B_  4
#define Q_  512
#define KK_ 1024
#define D_  512
#define H_  128
#define DV_ 512

// kp smem row stride in halves: 136 (272B) -> lane stride 272B,
// 272 mod 128 = 16 -> each 8-lane LDS.128 phase hits 8 distinct 16B quads:
// conflict-free (same arithmetic as the proven f32 stride-132 layout).
#define KPS 136

// Scratch (device globals; no allocation allowed in kernel_launch)
__device__ __half g_qph[B_ * Q_ * H_];    // 512 KB
__device__ __half g_kph[B_ * KK_ * H_];   // 1 MB
__device__ float  g_attn[B_ * Q_ * KK_];  // 8 MB

__device__ __forceinline__ __half2 tanh_h2(__half2 x) {
    unsigned xi = *(unsigned*)&x, yi;
    asm("tanh.approx.f16x2 %0, %1;" : "=r"(yi) : "r"(xi));
    return *(__half2*)&yi;
}
__device__ __forceinline__ __half2 as_h2(unsigned u) { return *(__half2*)&u; }

// ---- packed f32x2 helpers (sm_103a: FFMA2 reachable only via PTX) ----
__device__ __forceinline__ unsigned long long bcast2(float a) {
    unsigned long long r;
    asm("mov.b64 %0, {%1, %1};" : "=l"(r) : "f"(a));
    return r;
}
__device__ __forceinline__ void fma2(unsigned long long& d,
                                     unsigned long long a, unsigned long long b) {
    asm("fma.rn.f32x2 %0, %1, %2, %3;" : "=l"(d) : "l"(a), "l"(b), "l"(d));
}
__device__ __forceinline__ float2 unpack2(unsigned long long v) {
    float2 f;
    asm("mov.b64 {%0, %1}, %2;" : "=f"(f.x), "=f"(f.y) : "l"(v));
    return f;
}

// ---- cp.async helpers ----
__device__ __forceinline__ void cp_async16(void* smem, const void* gmem) {
    unsigned saddr = (unsigned)__cvta_generic_to_shared(smem);
    asm volatile("cp.async.cg.shared.global [%0], [%1], 16;\n" :: "r"(saddr), "l"(gmem));
}
__device__ __forceinline__ void cp_commit() {
    asm volatile("cp.async.commit_group;\n");
}
template<int N> __device__ __forceinline__ void cp_wait() {
    asm volatile("cp.async.wait_group %0;\n" :: "n"(N));
}

// ----------------------------------------------------------------------------
// Kernel 1: projections -> HALF out. C[row,h] = sum_d A[row,d]*W[d,h]
// BM=32, BN=64, BK=32, 128 threads, micro 4x4. All staging via cp.async,
// double-buffered with wait<1>. Grid 384 (measured 25.7-25.9us).
// ----------------------------------------------------------------------------
__global__ __launch_bounds__(128) void proj_kernel(
    const float* __restrict__ Aq, const float* __restrict__ Ak,
    const float* __restrict__ Wq, const float* __restrict__ Wk)
{
    __shared__ float As[2][32 * 32];
    __shared__ float Ws[2][32 * 64];

    int blk = blockIdx.x;
    const float* A;
    const float* W;
    __half* C;
    int rowbase, nb;
    if (blk < 128) { A = Aq; W = Wq; C = g_qph; rowbase = (blk >> 1) * 32; nb = (blk & 1) * 64; }
    else {
        int t = blk - 128;
        A = Ak; W = Wk; C = g_kph; rowbase = (t >> 1) * 32; nb = (t & 1) * 64;
    }

    int tid = threadIdx.x;
    int tx = tid & 15;            // col group: nb + tx*4
    int ty = tid >> 4;            // row group: ty*4 .. +3

    unsigned long long acc[4][2];
#pragma unroll
    for (int i = 0; i < 4; i++) { acc[i][0] = 0ull; acc[i][1] = 0ull; }

#define PROJ_STAGE(kk, buf)                                                     \
    do {                                                                        \
        _Pragma("unroll")                                                       \
        for (int i_ = 0; i_ < 2; i_++) {                                        \
            int idx_ = tid + i_ * 128;                                          \
            int r_ = idx_ >> 3, c_ = (idx_ & 7) << 2;                           \
            cp_async16(&As[buf][r_ * 32 + c_],                                  \
                       A + (size_t)(rowbase + r_) * D_ + (kk) + c_);            \
        }                                                                       \
        _Pragma("unroll")                                                       \
        for (int i_ = 0; i_ < 4; i_++) {                                        \
            int idx_ = tid + i_ * 128;                                          \
            int r_ = idx_ >> 4, c_ = (idx_ & 15) << 2;                          \
            cp_async16(&Ws[buf][r_ * 64 + c_],                                  \
                       W + (size_t)((kk) + r_) * H_ + nb + c_);                 \
        }                                                                       \
        cp_commit();                                                            \
    } while (0)

    PROJ_STAGE(0, 0);
    for (int s = 0; s < 16; s++) {
        int buf = s & 1;
        if (s + 1 < 16) { PROJ_STAGE((s + 1) * 32, (s + 1) & 1); cp_wait<1>(); }
        else            { cp_wait<0>(); }
        __syncthreads();
#pragma unroll
        for (int k = 0; k < 32; k++) {
            const ulonglong2 bv = *(const ulonglong2*)&Ws[buf][k * 64 + tx * 4];
#pragma unroll
            for (int i = 0; i < 4; i++) {
                unsigned long long pa = bcast2(As[buf][(ty * 4 + i) * 32 + k]);
                fma2(acc[i][0], pa, bv.x);
                fma2(acc[i][1], pa, bv.y);
            }
        }
        __syncthreads();
    }
#undef PROJ_STAGE

#pragma unroll
    for (int i = 0; i < 4; i++) {
        float2 lo = unpack2(acc[i][0]);
        float2 hi = unpack2(acc[i][1]);
        __half2 h0 = __floats2half2_rn(lo.x, lo.y);
        __half2 h1 = __floats2half2_rn(hi.x, hi.y);
        uint2 u = make_uint2(*(unsigned*)&h0, *(unsigned*)&h1);
        *(uint2*)(C + (size_t)(rowbase + ty * 4 + i) * H_ + nb + tx * 4) = u;
    }
}

// ----------------------------------------------------------------------------
// Kernel 2: scores + softmax. 128 threads = 4 warps, warp w owns q-row.
// Grid = B*Q/4 = 512. q/k in fp16: HADD2 + tanh.f16x2 (2 evals per MUFU),
// fp32 accumulate. kp chunks double-buffered via cp.async with wait<1>.
// kp smem rows padded to KPS=136 halves -> conflict-free LDS.128.
// ----------------------------------------------------------------------------
__global__ __launch_bounds__(128) void score_softmax_kernel(const float* __restrict__ wv_g)
{
    __shared__ __half kp_sm[2][32 * KPS];
    __shared__ __half q_sm[4 * 128];
    __shared__ float  w_sm[128];

    int tid = threadIdx.x;
    int w = tid >> 5;
    int l = tid & 31;

    int qb = blockIdx.x * 4;
    int b  = qb >> 9;
    int q0 = qb & 511;

    // stage 4 q-rows (half) + w_v (f32); first __syncthreads covers these
    if (tid < 64) {
        int r = tid >> 4, c = (tid & 15) << 3;
        *(uint4*)&q_sm[r * 128 + c] =
            *(const uint4*)&g_qph[(size_t)(b * Q_ + q0 + r) * H_ + c];
    }
    if (tid >= 96) {
        int t = tid - 96;
        *(float4*)&w_sm[t * 4] = *(const float4*)&wv_g[t * 4];
    }

    const __half* kp_base = g_kph + (size_t)b * KK_ * H_;

#define KP_STAGE(ch, buf) { _Pragma("unroll") for (int i_ = 0; i_ < 4; i_++) {  \
        int idx_ = tid + i_ * 128;                                              \
        int r_ = idx_ >> 4, c_ = (idx_ & 15) << 3;                              \
        cp_async16(&kp_sm[buf][r_ * KPS + c_],                                  \
                   kp_base + (size_t)((ch) * 32 + r_) * H_ + c_); }             \
        cp_commit(); }

    float s[32];

    KP_STAGE(0, 0);
    for (int ch = 0; ch < 32; ch++) {
        int buf = ch & 1;
        if (ch + 1 < 32) { KP_STAGE(ch + 1, buf ^ 1); cp_wait<1>(); }
        else             { cp_wait<0>(); }
        __syncthreads();

        const uint4* kr = (const uint4*)&kp_sm[buf][l * KPS];
        const uint4* qr = (const uint4*)&q_sm[w * 128];
        float s0 = 0.f, s1 = 0.f, s2 = 0.f, s3 = 0.f;
        float s4 = 0.f, s5 = 0.f, s6 = 0.f, s7 = 0.f;
#pragma unroll
        for (int h8 = 0; h8 < 16; h8++) {
            uint4 kv = kr[h8];
            uint4 qv = qr[h8];
            float2 f0 = __half22float2(tanh_h2(__hadd2(as_h2(qv.x), as_h2(kv.x))));
            float2 f1 = __half22float2(tanh_h2(__hadd2(as_h2(qv.y), as_h2(kv.y))));
            float2 f2 = __half22float2(tanh_h2(__hadd2(as_h2(qv.z), as_h2(kv.z))));
            float2 f3 = __half22float2(tanh_h2(__hadd2(as_h2(qv.w), as_h2(kv.w))));
            float4 w0 = *(const float4*)&w_sm[h8 * 8];
            float4 w1 = *(const float4*)&w_sm[h8 * 8 + 4];
            s0 += w0.x * f0.x; s1 += w0.y * f0.y;
            s2 += w0.z * f1.x; s3 += w0.w * f1.y;
            s4 += w1.x * f2.x; s5 += w1.y * f2.y;
            s6 += w1.z * f3.x; s7 += w1.w * f3.y;
        }
        s[ch] = ((s0 + s1) + (s2 + s3)) + ((s4 + s5) + (s6 + s7));
        __syncthreads();
    }
#undef KP_STAGE

    // softmax: lane l holds scores for k = ch*32 + l
    float m = -1e30f;
#pragma unroll
    for (int j = 0; j < 32; j++) m = fmaxf(m, s[j]);
#pragma unroll
    for (int o = 16; o; o >>= 1) m = fmaxf(m, __shfl_xor_sync(0xffffffffu, m, o));
    float sum = 0.f;
#pragma unroll
    for (int j = 0; j < 32; j++) { s[j] = __expf(s[j] - m); sum += s[j]; }
#pragma unroll
    for (int o = 16; o; o >>= 1) sum += __shfl_xor_sync(0xffffffffu, sum, o);
    float inv = 1.0f / sum;

    float* arow = g_attn + (size_t)(b * Q_ + q0 + w) * KK_;
#pragma unroll
    for (int j = 0; j < 32; j++) arow[j * 32 + l] = s[j] * inv;
}

// ----------------------------------------------------------------------------
// Kernel 3: out[b] = attn[b] @ values[b].  M=512, N=512, Kd=1024 per batch.
// R2 version: BM=BN=64, BK=32, 256 threads, micro 4x4 (2 f32x2 pairs),
// all cp.async staging, double-buffered with wait<1>. Grid (8,8,4)=256.
// ----------------------------------------------------------------------------
__global__ __launch_bounds__(256) void av_gemm_kernel(
    const float* __restrict__ values, float* __restrict__ out)
{
    __shared__ float As[2][64 * 32];
    __shared__ float Bs[2][32 * 64];

    int b  = blockIdx.z;
    int mb = blockIdx.y * 64;
    int nb = blockIdx.x * 64;

    const float* Ab = g_attn + (size_t)b * Q_ * KK_;     // [512,1024]
    const float* Bb = values + (size_t)b * KK_ * DV_;    // [1024,512]
    float* Ob = out + (size_t)b * Q_ * DV_;

    int tid = threadIdx.x;
    int tx = tid & 15;     // cols nb + tx*4 .. +3
    int ty = tid >> 4;     // rows mb + ty*4 .. +3

    unsigned long long acc[4][2];
#pragma unroll
    for (int i = 0; i < 4; i++) { acc[i][0] = 0ull; acc[i][1] = 0ull; }

#define AV_STAGE(kk, buf)                                                       \
    do {                                                                        \
        _Pragma("unroll")                                                       \
        for (int i_ = 0; i_ < 2; i_++) {                                        \
            int idx_ = tid + i_ * 256;                                          \
            int r_ = idx_ >> 3, c_ = (idx_ & 7) << 2;                           \
            cp_async16(&As[buf][r_ * 32 + c_],                                  \
                       Ab + (size_t)(mb + r_) * KK_ + (kk) + c_);               \
        }                                                                       \
        _Pragma("unroll")                                                       \
        for (int i_ = 0; i_ < 2; i_++) {                                        \
            int idx_ = tid + i_ * 256;                                          \
            int r_ = idx_ >> 4, c_ = (idx_ & 15) << 2;                          \
            cp_async16(&Bs[buf][r_ * 64 + c_],                                  \
                       Bb + (size_t)((kk) + r_) * DV_ + nb + c_);               \
        }                                                                       \
        cp_commit();                                                            \
    } while (0)

    AV_STAGE(0, 0);
    for (int s = 0; s < 32; s++) {
        int buf = s & 1;
        if (s + 1 < 32) { AV_STAGE((s + 1) * 32, (s + 1) & 1); cp_wait<1>(); }
        else            { cp_wait<0>(); }
        __syncthreads();
#pragma unroll
        for (int k = 0; k < 32; k++) {
            const ulonglong2 bv = *(const ulonglong2*)&Bs[buf][k * 64 + tx * 4];
#pragma unroll
            for (int i = 0; i < 4; i++) {
                unsigned long long pa = bcast2(As[buf][(ty * 4 + i) * 32 + k]);
                fma2(acc[i][0], pa, bv.x);
                fma2(acc[i][1], pa, bv.y);
            }
        }
        __syncthreads();
    }
#undef AV_STAGE

#pragma unroll
    for (int i = 0; i < 4; i++) {
        float2 lo = unpack2(acc[i][0]);
        float2 hi = unpack2(acc[i][1]);
        float4 v = make_float4(lo.x, lo.y, hi.x, hi.y);
        *(float4*)(Ob + (size_t)(mb + ty * 4 + i) * DV_ + nb + tx * 4) = v;
    }
}

// ----------------------------------------------------------------------------
extern "C" void kernel_launch(void* const* d_in, const int* in_sizes, int n_in,
                              void* d_out, int out_size)
{
    const float* queries = (const float*)d_in[0];  // [4,512,512]
    const float* keys    = (const float*)d_in[1];  // [4,1024,512]
    const float* values  = (const float*)d_in[2];  // [4,1024,512]
    const float* W_q     = (const float*)d_in[3];  // [512,128]
    const float* W_k     = (const float*)d_in[4];  // [512,128]
    const float* w_v     = (const float*)d_in[5];  // [128]
    float* out = (float*)d_out;                    // [4,512,512]

    proj_kernel<<<384, 128>>>(queries, keys, W_q, W_k);
    score_softmax_kernel<<<512, 128>>>(w_v);
    dim3 g3(8, 8, 4);
    av_gemm_kernel<<<g3, 256>>>(values, out);
}

// round 12
// speedup vs baseline: 1.8564x; 1.0140x over previous
#include <cuda_runtime.h>
#include <cuda_fp16.h>

#define B_  4
#define Q_  512
#define KK_ 1024
#define D_  512
#define H_  128
#define DV_ 512

// kp smem row stride in halves: 136 (272B) -> lane stride 272B,
// 272 mod 128 = 16 -> each 8-lane LDS.128 phase hits 8 distinct 16B quads:
// conflict-free (same arithmetic as the proven f32 stride-132 layout).
#define KPS 136

// Scratch (device globals; no allocation allowed in kernel_launch)
__device__ __half g_qph[B_ * Q_ * H_];    // 512 KB
__device__ __half g_kph[B_ * KK_ * H_];   // 1 MB
__device__ float  g_attn[B_ * Q_ * KK_];  // 8 MB

__device__ __forceinline__ __half2 tanh_h2(__half2 x) {
    unsigned xi = *(unsigned*)&x, yi;
    asm("tanh.approx.f16x2 %0, %1;" : "=r"(yi) : "r"(xi));
    return *(__half2*)&yi;
}
__device__ __forceinline__ __half2 as_h2(unsigned u) { return *(__half2*)&u; }

// ---- packed f32x2 helpers (sm_103a: FFMA2 reachable only via PTX) ----
__device__ __forceinline__ unsigned long long bcast2(float a) {
    unsigned long long r;
    asm("mov.b64 %0, {%1, %1};" : "=l"(r) : "f"(a));
    return r;
}
__device__ __forceinline__ void fma2(unsigned long long& d,
                                     unsigned long long a, unsigned long long b) {
    asm("fma.rn.f32x2 %0, %1, %2, %3;" : "=l"(d) : "l"(a), "l"(b), "l"(d));
}
__device__ __forceinline__ float2 unpack2(unsigned long long v) {
    float2 f;
    asm("mov.b64 {%0, %1}, %2;" : "=f"(f.x), "=f"(f.y) : "l"(v));
    return f;
}

// ---- cp.async helpers ----
__device__ __forceinline__ void cp_async16(void* smem, const void* gmem) {
    unsigned saddr = (unsigned)__cvta_generic_to_shared(smem);
    asm volatile("cp.async.cg.shared.global [%0], [%1], 16;\n" :: "r"(saddr), "l"(gmem));
}
__device__ __forceinline__ void cp_commit() {
    asm volatile("cp.async.commit_group;\n");
}
template<int N> __device__ __forceinline__ void cp_wait() {
    asm volatile("cp.async.wait_group %0;\n" :: "n"(N));
}

// ----------------------------------------------------------------------------
// Kernel 1: projections -> HALF out. C[row,h] = sum_d A[row,d]*W[d,h]
// BM=32, BN=64, BK=32, 128 threads, micro 4x4. All staging via cp.async,
// double-buffered with wait<1>. Grid 384 (measured 25.4-25.9us). UNCHANGED.
// ----------------------------------------------------------------------------
__global__ __launch_bounds__(128) void proj_kernel(
    const float* __restrict__ Aq, const float* __restrict__ Ak,
    const float* __restrict__ Wq, const float* __restrict__ Wk)
{
    __shared__ float As[2][32 * 32];
    __shared__ float Ws[2][32 * 64];

    int blk = blockIdx.x;
    const float* A;
    const float* W;
    __half* C;
    int rowbase, nb;
    if (blk < 128) { A = Aq; W = Wq; C = g_qph; rowbase = (blk >> 1) * 32; nb = (blk & 1) * 64; }
    else {
        int t = blk - 128;
        A = Ak; W = Wk; C = g_kph; rowbase = (t >> 1) * 32; nb = (t & 1) * 64;
    }

    int tid = threadIdx.x;
    int tx = tid & 15;            // col group: nb + tx*4
    int ty = tid >> 4;            // row group: ty*4 .. +3

    unsigned long long acc[4][2];
#pragma unroll
    for (int i = 0; i < 4; i++) { acc[i][0] = 0ull; acc[i][1] = 0ull; }

#define PROJ_STAGE(kk, buf)                                                     \
    do {                                                                        \
        _Pragma("unroll")                                                       \
        for (int i_ = 0; i_ < 2; i_++) {                                        \
            int idx_ = tid + i_ * 128;                                          \
            int r_ = idx_ >> 3, c_ = (idx_ & 7) << 2;                           \
            cp_async16(&As[buf][r_ * 32 + c_],                                  \
                       A + (size_t)(rowbase + r_) * D_ + (kk) + c_);            \
        }                                                                       \
        _Pragma("unroll")                                                       \
        for (int i_ = 0; i_ < 4; i_++) {                                        \
            int idx_ = tid + i_ * 128;                                          \
            int r_ = idx_ >> 4, c_ = (idx_ & 15) << 2;                          \
            cp_async16(&Ws[buf][r_ * 64 + c_],                                  \
                       W + (size_t)((kk) + r_) * H_ + nb + c_);                 \
        }                                                                       \
        cp_commit();                                                            \
    } while (0)

    PROJ_STAGE(0, 0);
    for (int s = 0; s < 16; s++) {
        int buf = s & 1;
        if (s + 1 < 16) { PROJ_STAGE((s + 1) * 32, (s + 1) & 1); cp_wait<1>(); }
        else            { cp_wait<0>(); }
        __syncthreads();
#pragma unroll
        for (int k = 0; k < 32; k++) {
            const ulonglong2 bv = *(const ulonglong2*)&Ws[buf][k * 64 + tx * 4];
#pragma unroll
            for (int i = 0; i < 4; i++) {
                unsigned long long pa = bcast2(As[buf][(ty * 4 + i) * 32 + k]);
                fma2(acc[i][0], pa, bv.x);
                fma2(acc[i][1], pa, bv.y);
            }
        }
        __syncthreads();
    }
#undef PROJ_STAGE

#pragma unroll
    for (int i = 0; i < 4; i++) {
        float2 lo = unpack2(acc[i][0]);
        float2 hi = unpack2(acc[i][1]);
        __half2 h0 = __floats2half2_rn(lo.x, lo.y);
        __half2 h1 = __floats2half2_rn(hi.x, hi.y);
        uint2 u = make_uint2(*(unsigned*)&h0, *(unsigned*)&h1);
        *(uint2*)(C + (size_t)(rowbase + ty * 4 + i) * H_ + nb + tx * 4) = u;
    }
}

// ----------------------------------------------------------------------------
// Kernel 2: scores + softmax. 256 threads = 8 warps, warp w owns q-row.
// Grid = B*Q/8 = 256. q/k in fp16: HADD2 + tanh.f16x2 (2 evals per MUFU),
// fp32 accumulate. kp chunks double-buffered via cp.async with wait<1>;
// staging amortized over 8 warps (2 cp.async per thread per chunk).
// kp smem rows padded to KPS=136 halves -> conflict-free LDS.128.
// ----------------------------------------------------------------------------
__global__ __launch_bounds__(256) void score_softmax_kernel(const float* __restrict__ wv_g)
{
    __shared__ __half kp_sm[2][32 * KPS];
    __shared__ __half q_sm[8 * 128];
    __shared__ float  w_sm[128];

    int tid = threadIdx.x;
    int w = tid >> 5;
    int l = tid & 31;

    int qb = blockIdx.x * 8;    // flattened (b,q) row base; 512%8==0 so no batch straddle
    int b  = qb >> 9;
    int q0 = qb & 511;

    // stage 8 q-rows (half) + w_v (f32); first __syncthreads covers these
    if (tid < 128) {
        int r = tid >> 4, c = (tid & 15) << 3;
        *(uint4*)&q_sm[r * 128 + c] =
            *(const uint4*)&g_qph[(size_t)(b * Q_ + q0 + r) * H_ + c];
    }
    if (tid >= 224) {
        int t = tid - 224;
        *(float4*)&w_sm[t * 4] = *(const float4*)&wv_g[t * 4];
    }

    const __half* kp_base = g_kph + (size_t)b * KK_ * H_;

#define KP_STAGE(ch, buf) { _Pragma("unroll") for (int i_ = 0; i_ < 2; i_++) {  \
        int idx_ = tid + i_ * 256;                                              \
        int r_ = idx_ >> 4, c_ = (idx_ & 15) << 3;                              \
        cp_async16(&kp_sm[buf][r_ * KPS + c_],                                  \
                   kp_base + (size_t)((ch) * 32 + r_) * H_ + c_); }             \
        cp_commit(); }

    float s[32];

    KP_STAGE(0, 0);
    for (int ch = 0; ch < 32; ch++) {
        int buf = ch & 1;
        if (ch + 1 < 32) { KP_STAGE(ch + 1, buf ^ 1); cp_wait<1>(); }
        else             { cp_wait<0>(); }
        __syncthreads();

        const uint4* kr = (const uint4*)&kp_sm[buf][l * KPS];
        const uint4* qr = (const uint4*)&q_sm[w * 128];
        float s0 = 0.f, s1 = 0.f, s2 = 0.f, s3 = 0.f;
        float s4 = 0.f, s5 = 0.f, s6 = 0.f, s7 = 0.f;
#pragma unroll
        for (int h8 = 0; h8 < 16; h8++) {
            uint4 kv = kr[h8];
            uint4 qv = qr[h8];
            float2 f0 = __half22float2(tanh_h2(__hadd2(as_h2(qv.x), as_h2(kv.x))));
            float2 f1 = __half22float2(tanh_h2(__hadd2(as_h2(qv.y), as_h2(kv.y))));
            float2 f2 = __half22float2(tanh_h2(__hadd2(as_h2(qv.z), as_h2(kv.z))));
            float2 f3 = __half22float2(tanh_h2(__hadd2(as_h2(qv.w), as_h2(kv.w))));
            float4 w0 = *(const float4*)&w_sm[h8 * 8];
            float4 w1 = *(const float4*)&w_sm[h8 * 8 + 4];
            s0 += w0.x * f0.x; s1 += w0.y * f0.y;
            s2 += w0.z * f1.x; s3 += w0.w * f1.y;
            s4 += w1.x * f2.x; s5 += w1.y * f2.y;
            s6 += w1.z * f3.x; s7 += w1.w * f3.y;
        }
        s[ch] = ((s0 + s1) + (s2 + s3)) + ((s4 + s5) + (s6 + s7));
        __syncthreads();
    }
#undef KP_STAGE

    // softmax: lane l holds scores for k = ch*32 + l (warp-private row)
    float m = -1e30f;
#pragma unroll
    for (int j = 0; j < 32; j++) m = fmaxf(m, s[j]);
#pragma unroll
    for (int o = 16; o; o >>= 1) m = fmaxf(m, __shfl_xor_sync(0xffffffffu, m, o));
    float sum = 0.f;
#pragma unroll
    for (int j = 0; j < 32; j++) { s[j] = __expf(s[j] - m); sum += s[j]; }
#pragma unroll
    for (int o = 16; o; o >>= 1) sum += __shfl_xor_sync(0xffffffffu, sum, o);
    float inv = 1.0f / sum;

    float* arow = g_attn + (size_t)(b * Q_ + q0 + w) * KK_;
#pragma unroll
    for (int j = 0; j < 32; j++) arow[j * 32 + l] = s[j] * inv;
}

// ----------------------------------------------------------------------------
// Kernel 3: out[b] = attn[b] @ values[b].  M=512, N=512, Kd=1024 per batch.
// R2 version: BM=BN=64, BK=32, 256 threads, micro 4x4 (2 f32x2 pairs),
// all cp.async staging, double-buffered with wait<1>. Grid (8,8,4)=256.
// UNCHANGED.
// ----------------------------------------------------------------------------
__global__ __launch_bounds__(256) void av_gemm_kernel(
    const float* __restrict__ values, float* __restrict__ out)
{
    __shared__ float As[2][64 * 32];
    __shared__ float Bs[2][32 * 64];

    int b  = blockIdx.z;
    int mb = blockIdx.y * 64;
    int nb = blockIdx.x * 64;

    const float* Ab = g_attn + (size_t)b * Q_ * KK_;     // [512,1024]
    const float* Bb = values + (size_t)b * KK_ * DV_;    // [1024,512]
    float* Ob = out + (size_t)b * Q_ * DV_;

    int tid = threadIdx.x;
    int tx = tid & 15;     // cols nb + tx*4 .. +3
    int ty = tid >> 4;     // rows mb + ty*4 .. +3

    unsigned long long acc[4][2];
#pragma unroll
    for (int i = 0; i < 4; i++) { acc[i][0] = 0ull; acc[i][1] = 0ull; }

#define AV_STAGE(kk, buf)                                                       \
    do {                                                                        \
        _Pragma("unroll")                                                       \
        for (int i_ = 0; i_ < 2; i_++) {                                        \
            int idx_ = tid + i_ * 256;                                          \
            int r_ = idx_ >> 3, c_ = (idx_ & 7) << 2;                           \
            cp_async16(&As[buf][r_ * 32 + c_],                                  \
                       Ab + (size_t)(mb + r_) * KK_ + (kk) + c_);               \
        }                                                                       \
        _Pragma("unroll")                                                       \
        for (int i_ = 0; i_ < 2; i_++) {                                        \
            int idx_ = tid + i_ * 256;                                          \
            int r_ = idx_ >> 4, c_ = (idx_ & 15) << 2;                          \
            cp_async16(&Bs[buf][r_ * 64 + c_],                                  \
                       Bb + (size_t)((kk) + r_) * DV_ + nb + c_);               \
        }                                                                       \
        cp_commit();                                                            \
    } while (0)

    AV_STAGE(0, 0);
    for (int s = 0; s < 32; s++) {
        int buf = s & 1;
        if (s + 1 < 32) { AV_STAGE((s + 1) * 32, (s + 1) & 1); cp_wait<1>(); }
        else            { cp_wait<0>(); }
        __syncthreads();
#pragma unroll
        for (int k = 0; k < 32; k++) {
            const ulonglong2 bv = *(const ulonglong2*)&Bs[buf][k * 64 + tx * 4];
#pragma unroll
            for (int i = 0; i < 4; i++) {
                unsigned long long pa = bcast2(As[buf][(ty * 4 + i) * 32 + k]);
                fma2(acc[i][0], pa, bv.x);
                fma2(acc[i][1], pa, bv.y);
            }
        }
        __syncthreads();
    }
#undef AV_STAGE

#pragma unroll
    for (int i = 0; i < 4; i++) {
        float2 lo = unpack2(acc[i][0]);
        float2 hi = unpack2(acc[i][1]);
        float4 v = make_float4(lo.x, lo.y, hi.x, hi.y);
        *(float4*)(Ob + (size_t)(mb + ty * 4 + i) * DV_ + nb + tx * 4) = v;
    }
}

// ----------------------------------------------------------------------------
extern "C" void kernel_launch(void* const* d_in, const int* in_sizes, int n_in,
                              void* d_out, int out_size)
{
    const float* queries = (const float*)d_in[0];  // [4,512,512]
    const float* keys    = (const float*)d_in[1];  // [4,1024,512]
    const float* values  = (const float*)d_in[2];  // [4,1024,512]
    const float* W_q     = (const float*)d_in[3];  // [512,128]
    const float* W_k     = (const float*)d_in[4];  // [512,128]
    const float* w_v     = (const float*)d_in[5];  // [128]
    float* out = (float*)d_out;                    // [4,512,512]

    proj_kernel<<<384, 128>>>(queries, keys, W_q, W_k);
    score_softmax_kernel<<<256, 256>>>(w_v);
    dim3 g3(8, 8, 4);
    av_gemm_kernel<<<g3, 256>>>(values, out);
}

// round 15
// speedup vs baseline: 1.8594x; 1.0016x over previous
#include <cuda_runtime.h>
#include <cuda_fp16.h>

#define B_  4
#define Q_  512
#define KK_ 1024
#define D_  512
#define H_  128
#define DV_ 512

// kp smem row stride in halves: 136 (272B) -> lane stride 272B,
// 272 mod 128 = 16 -> each 8-lane LDS.128 phase hits 8 distinct 16B quads:
// conflict-free (same arithmetic as the proven f32 stride-132 layout).
#define KPS 136

// Scratch (device globals; no allocation allowed in kernel_launch)
__device__ __half g_qph[B_ * Q_ * H_];    // 512 KB
__device__ __half g_kph[B_ * KK_ * H_];   // 1 MB
__device__ float  g_attn[B_ * Q_ * KK_];  // 8 MB

__device__ __forceinline__ __half2 tanh_h2(__half2 x) {
    unsigned xi = *(unsigned*)&x, yi;
    asm("tanh.approx.f16x2 %0, %1;" : "=r"(yi) : "r"(xi));
    return *(__half2*)&yi;
}
__device__ __forceinline__ __half2 as_h2(unsigned u) { return *(__half2*)&u; }

// ---- packed f32x2 helpers (sm_103a: FFMA2 reachable only via PTX) ----
__device__ __forceinline__ unsigned long long bcast2(float a) {
    unsigned long long r;
    asm("mov.b64 %0, {%1, %1};" : "=l"(r) : "f"(a));
    return r;
}
__device__ __forceinline__ void fma2(unsigned long long& d,
                                     unsigned long long a, unsigned long long b) {
    asm("fma.rn.f32x2 %0, %1, %2, %3;" : "=l"(d) : "l"(a), "l"(b), "l"(d));
}
__device__ __forceinline__ float2 unpack2(unsigned long long v) {
    float2 f;
    asm("mov.b64 {%0, %1}, %2;" : "=f"(f.x), "=f"(f.y) : "l"(v));
    return f;
}

// ---- cp.async helpers ----
__device__ __forceinline__ void cp_async16(void* smem, const void* gmem) {
    unsigned saddr = (unsigned)__cvta_generic_to_shared(smem);
    asm volatile("cp.async.cg.shared.global [%0], [%1], 16;\n" :: "r"(saddr), "l"(gmem));
}
__device__ __forceinline__ void cp_commit() {
    asm volatile("cp.async.commit_group;\n");
}
template<int N> __device__ __forceinline__ void cp_wait() {
    asm volatile("cp.async.wait_group %0;\n" :: "n"(N));
}

// ----------------------------------------------------------------------------
// Kernel 1: projections -> HALF out. C[row,h] = sum_d A[row,d]*W[d,h]
// BM=32, BN=64, BK=32, 128 threads, micro 4x4. All staging via cp.async,
// double-buffered with wait<1>. Grid 384 (measured 25.4-26.0us). UNCHANGED.
// ----------------------------------------------------------------------------
__global__ __launch_bounds__(128) void proj_kernel(
    const float* __restrict__ Aq, const float* __restrict__ Ak,
    const float* __restrict__ Wq, const float* __restrict__ Wk)
{
    __shared__ float As[2][32 * 32];
    __shared__ float Ws[2][32 * 64];

    int blk = blockIdx.x;
    const float* A;
    const float* W;
    __half* C;
    int rowbase, nb;
    if (blk < 128) { A = Aq; W = Wq; C = g_qph; rowbase = (blk >> 1) * 32; nb = (blk & 1) * 64; }
    else {
        int t = blk - 128;
        A = Ak; W = Wk; C = g_kph; rowbase = (t >> 1) * 32; nb = (t & 1) * 64;
    }

    int tid = threadIdx.x;
    int tx = tid & 15;            // col group: nb + tx*4
    int ty = tid >> 4;            // row group: ty*4 .. +3

    unsigned long long acc[4][2];
#pragma unroll
    for (int i = 0; i < 4; i++) { acc[i][0] = 0ull; acc[i][1] = 0ull; }

#define PROJ_STAGE(kk, buf)                                                     \
    do {                                                                        \
        _Pragma("unroll")                                                       \
        for (int i_ = 0; i_ < 2; i_++) {                                        \
            int idx_ = tid + i_ * 128;                                          \
            int r_ = idx_ >> 3, c_ = (idx_ & 7) << 2;                           \
            cp_async16(&As[buf][r_ * 32 + c_],                                  \
                       A + (size_t)(rowbase + r_) * D_ + (kk) + c_);            \
        }                                                                       \
        _Pragma("unroll")                                                       \
        for (int i_ = 0; i_ < 4; i_++) {                                        \
            int idx_ = tid + i_ * 128;                                          \
            int r_ = idx_ >> 4, c_ = (idx_ & 15) << 2;                          \
            cp_async16(&Ws[buf][r_ * 64 + c_],                                  \
                       W + (size_t)((kk) + r_) * H_ + nb + c_);                 \
        }                                                                       \
        cp_commit();                                                            \
    } while (0)

    PROJ_STAGE(0, 0);
    for (int s = 0; s < 16; s++) {
        int buf = s & 1;
        if (s + 1 < 16) { PROJ_STAGE((s + 1) * 32, (s + 1) & 1); cp_wait<1>(); }
        else            { cp_wait<0>(); }
        __syncthreads();
#pragma unroll
        for (int k = 0; k < 32; k++) {
            const ulonglong2 bv = *(const ulonglong2*)&Ws[buf][k * 64 + tx * 4];
#pragma unroll
            for (int i = 0; i < 4; i++) {
                unsigned long long pa = bcast2(As[buf][(ty * 4 + i) * 32 + k]);
                fma2(acc[i][0], pa, bv.x);
                fma2(acc[i][1], pa, bv.y);
            }
        }
        __syncthreads();
    }
#undef PROJ_STAGE

#pragma unroll
    for (int i = 0; i < 4; i++) {
        float2 lo = unpack2(acc[i][0]);
        float2 hi = unpack2(acc[i][1]);
        __half2 h0 = __floats2half2_rn(lo.x, lo.y);
        __half2 h1 = __floats2half2_rn(hi.x, hi.y);
        uint2 u = make_uint2(*(unsigned*)&h0, *(unsigned*)&h1);
        *(uint2*)(C + (size_t)(rowbase + ty * 4 + i) * H_ + nb + tx * 4) = u;
    }
}

// ----------------------------------------------------------------------------
// Kernel 2: scores + softmax. 256 threads = 8 warps, warp w owns q-row.
// Grid = B*Q/8 = 256. q/k/w in fp16. Per h8 (8 h-values): HADD2 + tanh.f16x2
// + HFMA2 into a half2 partial (fma pipe), ONE half2->float2 convert + 2 FADD
// flush into fp32 accumulators -> XU pipe demand per h8 drops 64 -> 40 cyc.
// kp chunks double-buffered via cp.async with wait<1>; KPS padding keeps
// LDS.128 conflict-free.
// ----------------------------------------------------------------------------
__global__ __launch_bounds__(256) void score_softmax_kernel(const float* __restrict__ wv_g)
{
    __shared__ __half kp_sm[2][32 * KPS];
    __shared__ __half q_sm[8 * 128];
    __shared__ __half w_smh[128];

    int tid = threadIdx.x;
    int w = tid >> 5;
    int l = tid & 31;

    int qb = blockIdx.x * 8;    // flattened (b,q) row base; 512%8==0 so no batch straddle
    int b  = qb >> 9;
    int q0 = qb & 511;

    // stage 8 q-rows (half) + w_v (f32 -> half); first __syncthreads covers these
    if (tid < 128) {
        int r = tid >> 4, c = (tid & 15) << 3;
        *(uint4*)&q_sm[r * 128 + c] =
            *(const uint4*)&g_qph[(size_t)(b * Q_ + q0 + r) * H_ + c];
    }
    if (tid >= 224) {
        int t = tid - 224;
        float4 wv = *(const float4*)&wv_g[t * 4];
        __half2 h0 = __floats2half2_rn(wv.x, wv.y);
        __half2 h1 = __floats2half2_rn(wv.z, wv.w);
        uint2 u = make_uint2(*(unsigned*)&h0, *(unsigned*)&h1);
        *(uint2*)&w_smh[t * 4] = u;
    }

    const __half* kp_base = g_kph + (size_t)b * KK_ * H_;

#define KP_STAGE(ch, buf) { _Pragma("unroll") for (int i_ = 0; i_ < 2; i_++) {  \
        int idx_ = tid + i_ * 256;                                              \
        int r_ = idx_ >> 4, c_ = (idx_ & 15) << 3;                              \
        cp_async16(&kp_sm[buf][r_ * KPS + c_],                                  \
                   kp_base + (size_t)((ch) * 32 + r_) * H_ + c_); }             \
        cp_commit(); }

    float s[32];

    KP_STAGE(0, 0);
    for (int ch = 0; ch < 32; ch++) {
        int buf = ch & 1;
        if (ch + 1 < 32) { KP_STAGE(ch + 1, buf ^ 1); cp_wait<1>(); }
        else             { cp_wait<0>(); }
        __syncthreads();

        const uint4* kr = (const uint4*)&kp_sm[buf][l * KPS];
        const uint4* qr = (const uint4*)&q_sm[w * 128];
        const uint4* wr = (const uint4*)w_smh;
        float a0 = 0.f, a1 = 0.f;
#pragma unroll
        for (int h8 = 0; h8 < 16; h8++) {
            uint4 kv = kr[h8];
            uint4 qv = qr[h8];
            uint4 wv = wr[h8];
            __half2 hacc = __float2half2_rn(0.f);
            hacc = __hfma2(as_h2(wv.x), tanh_h2(__hadd2(as_h2(qv.x), as_h2(kv.x))), hacc);
            hacc = __hfma2(as_h2(wv.y), tanh_h2(__hadd2(as_h2(qv.y), as_h2(kv.y))), hacc);
            hacc = __hfma2(as_h2(wv.z), tanh_h2(__hadd2(as_h2(qv.z), as_h2(kv.z))), hacc);
            hacc = __hfma2(as_h2(wv.w), tanh_h2(__hadd2(as_h2(qv.w), as_h2(kv.w))), hacc);
            float2 f = __half22float2(hacc);
            a0 += f.x;
            a1 += f.y;
        }
        s[ch] = a0 + a1;
        __syncthreads();
    }
#undef KP_STAGE

    // softmax: lane l holds scores for k = ch*32 + l (warp-private row)
    float m = -1e30f;
#pragma unroll
    for (int j = 0; j < 32; j++) m = fmaxf(m, s[j]);
#pragma unroll
    for (int o = 16; o; o >>= 1) m = fmaxf(m, __shfl_xor_sync(0xffffffffu, m, o));
    float sum = 0.f;
#pragma unroll
    for (int j = 0; j < 32; j++) { s[j] = __expf(s[j] - m); sum += s[j]; }
#pragma unroll
    for (int o = 16; o; o >>= 1) sum += __shfl_xor_sync(0xffffffffu, sum, o);
    float inv = 1.0f / sum;

    float* arow = g_attn + (size_t)(b * Q_ + q0 + w) * KK_;
#pragma unroll
    for (int j = 0; j < 32; j++) arow[j * 32 + l] = s[j] * inv;
}

// ----------------------------------------------------------------------------
// Kernel 3: out[b] = attn[b] @ values[b].  M=512, N=512, Kd=1024 per batch.
// R2 version: BM=BN=64, BK=32, 256 threads, micro 4x4 (2 f32x2 pairs),
// all cp.async staging, double-buffered with wait<1>. Grid (8,8,4)=256.
// UNCHANGED.
// ----------------------------------------------------------------------------
__global__ __launch_bounds__(256) void av_gemm_kernel(
    const float* __restrict__ values, float* __restrict__ out)
{
    __shared__ float As[2][64 * 32];
    __shared__ float Bs[2][32 * 64];

    int b  = blockIdx.z;
    int mb = blockIdx.y * 64;
    int nb = blockIdx.x * 64;

    const float* Ab = g_attn + (size_t)b * Q_ * KK_;     // [512,1024]
    const float* Bb = values + (size_t)b * KK_ * DV_;    // [1024,512]
    float* Ob = out + (size_t)b * Q_ * DV_;

    int tid = threadIdx.x;
    int tx = tid & 15;     // cols nb + tx*4 .. +3
    int ty = tid >> 4;     // rows mb + ty*4 .. +3

    unsigned long long acc[4][2];
#pragma unroll
    for (int i = 0; i < 4; i++) { acc[i][0] = 0ull; acc[i][1] = 0ull; }

#define AV_STAGE(kk, buf)                                                       \
    do {                                                                        \
        _Pragma("unroll")                                                       \
        for (int i_ = 0; i_ < 2; i_++) {                                        \
            int idx_ = tid + i_ * 256;                                          \
            int r_ = idx_ >> 3, c_ = (idx_ & 7) << 2;                           \
            cp_async16(&As[buf][r_ * 32 + c_],                                  \
                       Ab + (size_t)(mb + r_) * KK_ + (kk) + c_);               \
        }                                                                       \
        _Pragma("unroll")                                                       \
        for (int i_ = 0; i_ < 2; i_++) {                                        \
            int idx_ = tid + i_ * 256;                                          \
            int r_ = idx_ >> 4, c_ = (idx_ & 15) << 2;                          \
            cp_async16(&Bs[buf][r_ * 64 + c_],                                  \
                       Bb + (size_t)((kk) + r_) * DV_ + nb + c_);               \
        }                                                                       \
        cp_commit();                                                            \
    } while (0)

    AV_STAGE(0, 0);
    for (int s = 0; s < 32; s++) {
        int buf = s & 1;
        if (s + 1 < 32) { AV_STAGE((s + 1) * 32, (s + 1) & 1); cp_wait<1>(); }
        else            { cp_wait<0>(); }
        __syncthreads();
#pragma unroll
        for (int k = 0; k < 32; k++) {
            const ulonglong2 bv = *(const ulonglong2*)&Bs[buf][k * 64 + tx * 4];
#pragma unroll
            for (int i = 0; i < 4; i++) {
                unsigned long long pa = bcast2(As[buf][(ty * 4 + i) * 32 + k]);
                fma2(acc[i][0], pa, bv.x);
                fma2(acc[i][1], pa, bv.y);
            }
        }
        __syncthreads();
    }
#undef AV_STAGE

#pragma unroll
    for (int i = 0; i < 4; i++) {
        float2 lo = unpack2(acc[i][0]);
        float2 hi = unpack2(acc[i][1]);
        float4 v = make_float4(lo.x, lo.y, hi.x, hi.y);
        *(float4*)(Ob + (size_t)(mb + ty * 4 + i) * DV_ + nb + tx * 4) = v;
    }
}

// ----------------------------------------------------------------------------
extern "C" void kernel_launch(void* const* d_in, const int* in_sizes, int n_in,
                              void* d_out, int out_size)
{
    const float* queries = (const float*)d_in[0];  // [4,512,512]
    const float* keys    = (const float*)d_in[1];  // [4,1024,512]
    const float* values  = (const float*)d_in[2];  // [4,1024,512]
    const float* W_q     = (const float*)d_in[3];  // [512,128]
    const float* W_k     = (const float*)d_in[4];  // [512,128]
    const float* w_v     = (const float*)d_in[5];  // [128]
    float* out = (float*)d_out;                    // [4,512,512]

    proj_kernel<<<384, 128>>>(queries, keys, W_q, W_k);
    score_softmax_kernel<<<256, 256>>>(w_v);
    dim3 g3(8, 8, 4);
    av_gemm_kernel<<<g3, 256>>>(values, out);
}